// round 13
// baseline (speedup 1.0000x reference)
#include <cuda_runtime.h>
#include <cuda_fp16.h>
#include <cstdint>

#define CCH 32
#define DD 48
#define HHH 48
#define WWW 48
#define HW (HHH*WWW)           // 2304
#define DHW (DD*HHH*WWW)       // 110592
#define NTOT (2*CCH*DHW)       // 7077888 elements
#define EPSf 1e-6f
#define THREADS 256

// Pre-transposed mix weights: g_WT[m*32 + o] = w_mix[o*256 + m]
__device__ float g_WT[256 * 32];
// Quad-corner half image: g_x4[i] = {half2(v(y0,x0),v(y0,x1)), half2(v(y1,x0),v(y1,x1))}
// with x1 = min(x0+1,47), y1 = min(y0+1,47) clamps baked in. 8 B/voxel = 56.6 MB.
__device__ __align__(8) uint2 g_x4[NTOT];

__global__ void prep_WT_kernel(const float* __restrict__ w_mix) {
    int i = blockIdx.x * 256 + threadIdx.x;
    if (i < 256 * 32) {
        int m = i >> 5, o = i & 31;
        g_WT[m * 32 + o] = w_mix[o * 256 + m];
    }
}

__global__ __launch_bounds__(256) void prep_x4_kernel(const float* __restrict__ x) {
    int i = blockIdx.x * 256 + threadIdx.x;
    if (i >= NTOT) return;
    int xx = i % WWW;
    int yy = (i / WWW) % HHH;
    int dx = (xx < WWW - 1) ? 1 : 0;
    int dy = (yy < HHH - 1) ? WWW : 0;
    float a = x[i];
    float b = x[i + dx];
    float c = x[i + dy];
    float d = x[i + dy + dx];
    half2 lo = __floats2half2_rn(a, b);
    half2 hi = __floats2half2_rn(c, d);
    uint2 v;
    v.x = *reinterpret_cast<uint32_t*>(&lo);
    v.y = *reinterpret_cast<uint32_t*>(&hi);
    g_x4[i] = v;
}

// packed fp32x2 helpers
__device__ __forceinline__ void ffma2(unsigned long long &acc, unsigned long long w, unsigned long long v) {
    asm("fma.rn.f32x2 %0, %1, %2, %0;" : "+l"(acc) : "l"(w), "l"(v));
}
__device__ __forceinline__ unsigned long long pack2(float a) {
    unsigned long long r; asm("mov.b64 %0, {%1, %1};" : "=l"(r) : "f"(a)); return r;
}
__device__ __forceinline__ float2 unpack2(unsigned long long a) {
    float2 f; asm("mov.b64 {%0, %1}, %2;" : "=f"(f.x), "=f"(f.y) : "l"(a)); return f;
}
__device__ __forceinline__ float2 h2f2(uint32_t h) {
    half2 v = *reinterpret_cast<half2*>(&h);
    return __half22float2(v);
}

__device__ __forceinline__ float reflectf(float t, float size) {
    float c = fabsf(t + 0.5f);
    float m = fmodf(c, 2.0f * size);
    return fminf(m, 2.0f * size - m) - 0.5f;
}

// Dynamic shared layout (16B aligned):
#define OFF_WT   0
#define OFF_S    32768
#define OFF_WF   65536
#define OFF_BF   67072
#define OFF_BMIX 67136
#define OFF_SG   67264
#define SMEM_DYN 67296

__global__ __launch_bounds__(THREADS)
void geo_sample3d_kernel(const float* __restrict__ x,
                         const float* __restrict__ w_field,
                         const float* __restrict__ b_field,
                         const float* __restrict__ gates,
                         const float* __restrict__ b_mix,
                         float* __restrict__ out)
{
    extern __shared__ __align__(16) char dsm[];
    float* s_WT   = (float*)(dsm + OFF_WT);
    float* s_wf   = (float*)(dsm + OFF_WF);
    float* s_bf   = (float*)(dsm + OFF_BF);
    float* s_bmix = (float*)(dsm + OFF_BMIX);
    float* s_sg   = (float*)(dsm + OFF_SG);

    const int tid  = threadIdx.x;
    const int lane = tid & 31;
    const int wrp  = tid >> 5;
    float* warpS = (float*)(dsm + OFF_S) + wrp * 1024;   // 2 bufs * 512 floats

    #pragma unroll 4
    for (int i = tid; i < 256 * 32; i += THREADS) s_WT[i] = g_WT[i];
    for (int i = tid; i < 12 * CCH; i += THREADS) s_wf[i] = w_field[i];
    if (tid < 12)  s_bf[tid]   = b_field[tid];
    if (tid < CCH) s_bmix[tid] = b_mix[tid];
    if (tid < 8)   s_sg[tid]   = 1.0f / (1.0f + expf(-gates[tid]));
    __syncthreads();

    const int idx = blockIdx.x * THREADS + tid;   // total_vox = 864*256 exactly

    const int n   = idx / DHW;
    const int zyx = idx - n * DHW;
    const int z   = zyx / HW;
    const int r2i = zyx - z * HW;
    const int y   = r2i / WWW;
    const int w   = r2i - y * WWW;

    const float* __restrict__ xn  = x + (size_t)n * CCH * DHW;
    const uint2* __restrict__ x4n = g_x4 + (size_t)n * CCH * DHW;

    // ---- Phase 1: field conv f[12] ----
    float f[12];
    #pragma unroll
    for (int o = 0; o < 12; o++) f[o] = s_bf[o];
    #pragma unroll 4
    for (int c = 0; c < CCH; c++) {
        float xc = xn[c * DHW + zyx];
        #pragma unroll
        for (int o = 0; o < 12; o++) f[o] = fmaf(s_wf[o * CCH + c], xc, f[o]);
    }

    // ---- Phase 2: geometry + folded token coefficients ----
    int   ib[6], oz[6];
    float fx[6], fy[6], fz[6];
    float cA[3], cG[9], cLs[3];
    float sumIr2 = 0.0f;

    const float gx0 = (w + 0.5f) * (2.0f / WWW) - 1.0f;
    const float gy0 = (y + 0.5f) * (2.0f / HHH) - 1.0f;
    const float gz0 = (z + 0.5f) * (2.0f / DD)  - 1.0f;

    #pragma unroll
    for (int k = 0; k < 3; k++) {
        float vx = f[4*k+0], vy = f[4*k+1], vz = f[4*k+2], fr = f[4*k+3];
        float inv_norm = rsqrtf(vx*vx + vy*vy + vz*vz + EPSf);
        float ux = vx * inv_norm, uy = vy * inv_norm, uz = vz * inv_norm;
        float r  = 0.5f + 1.5f / (1.0f + expf(-fr));
        float dx = 2.0f * r * ux / ((float)WWW + EPSf);
        float dy = 2.0f * r * uy / ((float)HHH + EPSf);
        float dz = 2.0f * r * uz / ((float)DD  + EPSf);
        float invr = 1.0f / (r + EPSf);
        float ir2  = invr * invr;
        sumIr2 += ir2;

        cA[k]     = 0.5f * s_sg[1+k];
        cG[0*3+k] = s_sg[4] * 0.5f * invr * ux;
        cG[1*3+k] = s_sg[5] * 0.5f * invr * uy;
        cG[2*3+k] = s_sg[6] * 0.5f * invr * uz;
        cLs[k]    = s_sg[7] * (1.0f/3.0f) * ir2;

        #pragma unroll
        for (int s2 = 0; s2 < 2; s2++) {
            float sgn = s2 ? -1.0f : 1.0f;
            int   si  = 2*k + s2;
            float txu = ((gx0 + sgn*dx + 1.0f) * (float)WWW - 1.0f) * 0.5f;
            float tyu = ((gy0 + sgn*dy + 1.0f) * (float)HHH - 1.0f) * 0.5f;
            float tzu = ((gz0 + sgn*dz + 1.0f) * (float)DD  - 1.0f) * 0.5f;
            float ixs = reflectf(txu, (float)WWW);
            float iys = reflectf(tyu, (float)HHH);
            float izs = reflectf(tzu, (float)DD);

            float x0f = floorf(ixs), y0f = floorf(iys), z0f = floorf(izs);
            fx[si] = ixs - x0f;  fy[si] = iys - y0f;  fz[si] = izs - z0f;

            int x0i = (int)x0f; x0i = max(0, min(x0i, WWW-1));
            int y0i = (int)y0f; y0i = max(0, min(y0i, HHH-1));
            int z0i = (int)z0f; z0i = max(0, min(z0i, DD-1));  int z1i = min(z0i+1, DD-1);

            ib[si] = z0i * HW + y0i * WWW + x0i;   // x/y pairs baked into g_x4
            oz[si] = (z1i - z0i) * HW;
        }
    }

    const float cLx = -s_sg[7] * (2.0f/3.0f) * sumIr2;
    const float cx  = s_sg[0];

    // ---- Phase 3: per channel-pair: quad-corner gathers -> warp stage -> warp GEMM ----
    const int voxg = lane >> 2;    // 0..7 : 4-voxel group within warp
    const int outg = lane & 3;     // 0..3 : 8-output group

    unsigned long long acc[16];
    #pragma unroll
    for (int j = 0; j < 16; j++) acc[j] = 0ull;

    #pragma unroll 1
    for (int p = 0; p < 16; p++) {
        float tv[16];
        #pragma unroll
        for (int half_ = 0; half_ < 2; half_++) {
            const int c = 2*p + half_;
            const uint2* __restrict__ b4 = x4n + c * DHW;
            float xc = xn[c * DHW + zyx];

            float sv[6];
            #pragma unroll
            for (int si = 0; si < 6; si++) {
                const uint2* pp = b4 + ib[si];
                uint2 q0 = pp[0];        // z0 plane: {y0 pair, y1 pair}
                uint2 q1 = pp[oz[si]];   // z1 plane
                float2 v00 = h2f2(q0.x);
                float2 v01 = h2f2(q0.y);
                float2 v10 = h2f2(q1.x);
                float2 v11 = h2f2(q1.y);
                float c00 = v00.x + fx[si] * (v00.y - v00.x);
                float c01 = v01.x + fx[si] * (v01.y - v01.x);
                float c10 = v10.x + fx[si] * (v10.y - v10.x);
                float c11 = v11.x + fx[si] * (v11.y - v11.x);
                float c0  = c00 + fy[si] * (c01 - c00);
                float c1  = c10 + fy[si] * (c11 - c10);
                sv[si] = c0 + fz[si] * (c1 - c0);
            }

            float s0 = sv[0] + sv[1], m0 = sv[0] - sv[1];
            float s1 = sv[2] + sv[3], m1 = sv[2] - sv[3];
            float s2 = sv[4] + sv[5], m2 = sv[4] - sv[5];

            tv[0*2+half_] = cx * xc;
            tv[1*2+half_] = cA[0] * s0;
            tv[2*2+half_] = cA[1] * s1;
            tv[3*2+half_] = cA[2] * s2;
            tv[4*2+half_] = cG[0]*m0 + cG[1]*m1 + cG[2]*m2;
            tv[5*2+half_] = cG[3]*m0 + cG[4]*m1 + cG[5]*m2;
            tv[6*2+half_] = cG[6]*m0 + cG[7]*m1 + cG[8]*m2;
            tv[7*2+half_] = cLs[0]*s0 + cLs[1]*s1 + cLs[2]*s2 + cLx * xc;
        }

        // warp-private double-buffered stage; one syncwarp per iteration
        float* Sbuf = warpS + (p & 1) * 512;
        #pragma unroll
        for (int s = 0; s < 16; s++) Sbuf[s * 32 + lane] = tv[s];
        __syncwarp();

        #pragma unroll
        for (int s = 0; s < 16; s++) {
            const int t     = s >> 1;
            const int half_ = s & 1;
            const float* wb = s_WT + ((t*32 + 2*p + half_) << 5) + (outg << 3);
            ulonglong2 q0 = *(const ulonglong2*)wb;
            ulonglong2 q1 = *(const ulonglong2*)(wb + 4);
            const float4 av = *(const float4*)(Sbuf + s * 32 + (voxg << 2));
            unsigned long long a0 = pack2(av.x), a1 = pack2(av.y),
                               a2 = pack2(av.z), a3 = pack2(av.w);
            ffma2(acc[0],  q0.x, a0); ffma2(acc[1],  q0.y, a0);
            ffma2(acc[2],  q1.x, a0); ffma2(acc[3],  q1.y, a0);
            ffma2(acc[4],  q0.x, a1); ffma2(acc[5],  q0.y, a1);
            ffma2(acc[6],  q1.x, a1); ffma2(acc[7],  q1.y, a1);
            ffma2(acc[8],  q0.x, a2); ffma2(acc[9],  q0.y, a2);
            ffma2(acc[10], q1.x, a2); ffma2(acc[11], q1.y, a2);
            ffma2(acc[12], q0.x, a3); ffma2(acc[13], q0.y, a3);
            ffma2(acc[14], q1.x, a3); ffma2(acc[15], q1.y, a3);
        }
    }

    // ---- Phase 4: epilogue — my tile = 4 consecutive voxels x 8 outputs ----
    const int vt   = blockIdx.x * THREADS + wrp * 32 + (voxg << 2);
    const int n2   = vt / DHW;
    const int zyx2 = vt - n2 * DHW;
    const float* __restrict__ xn2 = x + (size_t)n2 * CCH * DHW;
    float* __restrict__ on2       = out + (size_t)n2 * CCH * DHW;
    #pragma unroll
    for (int jj = 0; jj < 4; jj++) {
        int o0 = (outg << 3) + 2*jj;
        float2 d0 = unpack2(acc[0*4 + jj]);
        float2 d1 = unpack2(acc[1*4 + jj]);
        float2 d2 = unpack2(acc[2*4 + jj]);
        float2 d3 = unpack2(acc[3*4 + jj]);
        {
            float4 xv = *(const float4*)(xn2 + (size_t)o0 * DHW + zyx2);
            float b = s_bmix[o0];
            float4 ov = make_float4(xv.x + d0.x + b, xv.y + d1.x + b,
                                    xv.z + d2.x + b, xv.w + d3.x + b);
            *(float4*)(on2 + (size_t)o0 * DHW + zyx2) = ov;
        }
        {
            int o1 = o0 + 1;
            float4 xv = *(const float4*)(xn2 + (size_t)o1 * DHW + zyx2);
            float b = s_bmix[o1];
            float4 ov = make_float4(xv.x + d0.y + b, xv.y + d1.y + b,
                                    xv.z + d2.y + b, xv.w + d3.y + b);
            *(float4*)(on2 + (size_t)o1 * DHW + zyx2) = ov;
        }
    }
}

extern "C" void kernel_launch(void* const* d_in, const int* in_sizes, int n_in,
                              void* d_out, int out_size)
{
    const float* x       = (const float*)d_in[0];
    const float* w_field = (const float*)d_in[1];
    const float* b_field = (const float*)d_in[2];
    const float* gates   = (const float*)d_in[3];
    const float* w_mix   = (const float*)d_in[4];
    const float* b_mix   = (const float*)d_in[5];
    float* out = (float*)d_out;

    (void)cudaFuncSetAttribute(geo_sample3d_kernel,
                               cudaFuncAttributeMaxDynamicSharedMemorySize, SMEM_DYN);

    prep_WT_kernel<<<32, 256>>>(w_mix);
    prep_x4_kernel<<<(NTOT + 255) / 256, 256>>>(x);

    int total_vox = in_sizes[0] / CCH;                 // 221184
    int blocks = total_vox / THREADS;                  // 864 (exact)
    geo_sample3d_kernel<<<blocks, THREADS, SMEM_DYN>>>(x, w_field, b_field, gates,
                                                       b_mix, out);
}

// round 14
// speedup vs baseline: 1.0872x; 1.0872x over previous
#include <cuda_runtime.h>
#include <cuda_fp16.h>
#include <cstdint>

#define CCH 32
#define DD 48
#define HHH 48
#define WWW 48
#define HW (HHH*WWW)           // 2304
#define DHW (DD*HHH*WWW)       // 110592
#define NTOT (2*CCH*DHW)       // 7077888 elements
#define NPAIR (NTOT/2)         // 3538944 pair entries
#define EPSf 1e-6f
#define THREADS 256

// Pre-transposed mix weights: g_WT[m*32 + o] = w_mix[o*256 + m]
__device__ float g_WT[256 * 32];
// Channel-pair interleaved quad-corner half image:
// g_x8[(n*16 + p)*DHW + zyx] = { quad(c=2p), quad(c=2p+1) } where
// quad(c) = { half2(v(y0,x0),v(y0,x1)), half2(v(y1,x0),v(y1,x1)) }, clamps baked.
__device__ __align__(16) uint4 g_x8[NPAIR];

__global__ __launch_bounds__(256) void prep_kernel(const float* __restrict__ x,
                                                   const float* __restrict__ w_mix) {
    if (blockIdx.x < 32) {
        int i = blockIdx.x * 256 + threadIdx.x;
        int m = i >> 5, o = i & 31;
        g_WT[m * 32 + o] = w_mix[o * 256 + m];
        return;
    }
    int i = (blockIdx.x - 32) * 256 + threadIdx.x;
    if (i >= NPAIR) return;
    int pidx = i / DHW;              // n*16 + p
    int zyx  = i - pidx * DHW;
    int n    = pidx >> 4;
    int p    = pidx & 15;
    int xx = zyx % WWW;
    int yy = (zyx / WWW) % HHH;
    int dx = (xx < WWW - 1) ? 1 : 0;
    int dy = (yy < HHH - 1) ? WWW : 0;
    const float* b0 = x + ((size_t)n * CCH + 2 * p) * DHW + zyx;
    const float* b1 = b0 + DHW;
    half2 a0 = __floats2half2_rn(b0[0],  b0[dx]);
    half2 a1 = __floats2half2_rn(b0[dy], b0[dy + dx]);
    half2 c0 = __floats2half2_rn(b1[0],  b1[dx]);
    half2 c1 = __floats2half2_rn(b1[dy], b1[dy + dx]);
    uint4 v;
    v.x = *reinterpret_cast<uint32_t*>(&a0);
    v.y = *reinterpret_cast<uint32_t*>(&a1);
    v.z = *reinterpret_cast<uint32_t*>(&c0);
    v.w = *reinterpret_cast<uint32_t*>(&c1);
    g_x8[i] = v;
}

// packed fp32x2 helpers
__device__ __forceinline__ void ffma2(unsigned long long &acc, unsigned long long w, unsigned long long v) {
    asm("fma.rn.f32x2 %0, %1, %2, %0;" : "+l"(acc) : "l"(w), "l"(v));
}
__device__ __forceinline__ unsigned long long pack2(float a) {
    unsigned long long r; asm("mov.b64 %0, {%1, %1};" : "=l"(r) : "f"(a)); return r;
}
__device__ __forceinline__ float2 unpack2(unsigned long long a) {
    float2 f; asm("mov.b64 {%0, %1}, %2;" : "=f"(f.x), "=f"(f.y) : "l"(a)); return f;
}
__device__ __forceinline__ float2 h2f2(uint32_t h) {
    half2 v = *reinterpret_cast<half2*>(&h);
    return __half22float2(v);
}

__device__ __forceinline__ float reflectf(float t, float size) {
    float c = fabsf(t + 0.5f);
    float m = fmodf(c, 2.0f * size);
    return fminf(m, 2.0f * size - m) - 0.5f;
}

// Dynamic shared layout (16B aligned):
#define OFF_WT   0
#define OFF_S    32768
#define OFF_WF   65536
#define OFF_BF   67072
#define OFF_BMIX 67136
#define OFF_SG   67264
#define SMEM_DYN 67296

__global__ __launch_bounds__(THREADS)
void geo_sample3d_kernel(const float* __restrict__ x,
                         const float* __restrict__ w_field,
                         const float* __restrict__ b_field,
                         const float* __restrict__ gates,
                         const float* __restrict__ b_mix,
                         float* __restrict__ out)
{
    extern __shared__ __align__(16) char dsm[];
    float* s_WT   = (float*)(dsm + OFF_WT);
    float* s_wf   = (float*)(dsm + OFF_WF);
    float* s_bf   = (float*)(dsm + OFF_BF);
    float* s_bmix = (float*)(dsm + OFF_BMIX);
    float* s_sg   = (float*)(dsm + OFF_SG);

    const int tid  = threadIdx.x;
    const int lane = tid & 31;
    const int wrp  = tid >> 5;
    float* warpS = (float*)(dsm + OFF_S) + wrp * 1024;   // 2 bufs * 512 floats

    #pragma unroll 4
    for (int i = tid; i < 256 * 32; i += THREADS) s_WT[i] = g_WT[i];
    for (int i = tid; i < 12 * CCH; i += THREADS) s_wf[i] = w_field[i];
    if (tid < 12)  s_bf[tid]   = b_field[tid];
    if (tid < CCH) s_bmix[tid] = b_mix[tid];
    if (tid < 8)   s_sg[tid]   = 1.0f / (1.0f + expf(-gates[tid]));
    __syncthreads();

    const int idx = blockIdx.x * THREADS + tid;   // total_vox = 864*256 exactly

    const int n   = idx / DHW;
    const int zyx = idx - n * DHW;
    const int z   = zyx / HW;
    const int r2i = zyx - z * HW;
    const int y   = r2i / WWW;
    const int w   = r2i - y * WWW;

    const float* __restrict__ xn  = x + (size_t)n * CCH * DHW;
    const uint4* __restrict__ x8n = g_x8 + (size_t)n * 16 * DHW;

    // ---- Phase 1: field conv f[12] ----
    float f[12];
    #pragma unroll
    for (int o = 0; o < 12; o++) f[o] = s_bf[o];
    #pragma unroll 4
    for (int c = 0; c < CCH; c++) {
        float xc = xn[c * DHW + zyx];
        #pragma unroll
        for (int o = 0; o < 12; o++) f[o] = fmaf(s_wf[o * CCH + c], xc, f[o]);
    }

    // ---- Phase 2: geometry + folded token coefficients ----
    int   ib[6], oz[6];
    float fx[6], fy[6], fz[6];
    float cA[3], cG[9], cLs[3];
    float sumIr2 = 0.0f;

    const float gx0 = (w + 0.5f) * (2.0f / WWW) - 1.0f;
    const float gy0 = (y + 0.5f) * (2.0f / HHH) - 1.0f;
    const float gz0 = (z + 0.5f) * (2.0f / DD)  - 1.0f;

    #pragma unroll
    for (int k = 0; k < 3; k++) {
        float vx = f[4*k+0], vy = f[4*k+1], vz = f[4*k+2], fr = f[4*k+3];
        float inv_norm = rsqrtf(vx*vx + vy*vy + vz*vz + EPSf);
        float ux = vx * inv_norm, uy = vy * inv_norm, uz = vz * inv_norm;
        float r  = 0.5f + 1.5f / (1.0f + expf(-fr));
        float dx = 2.0f * r * ux / ((float)WWW + EPSf);
        float dy = 2.0f * r * uy / ((float)HHH + EPSf);
        float dz = 2.0f * r * uz / ((float)DD  + EPSf);
        float invr = 1.0f / (r + EPSf);
        float ir2  = invr * invr;
        sumIr2 += ir2;

        cA[k]     = 0.5f * s_sg[1+k];
        cG[0*3+k] = s_sg[4] * 0.5f * invr * ux;
        cG[1*3+k] = s_sg[5] * 0.5f * invr * uy;
        cG[2*3+k] = s_sg[6] * 0.5f * invr * uz;
        cLs[k]    = s_sg[7] * (1.0f/3.0f) * ir2;

        #pragma unroll
        for (int s2 = 0; s2 < 2; s2++) {
            float sgn = s2 ? -1.0f : 1.0f;
            int   si  = 2*k + s2;
            float txu = ((gx0 + sgn*dx + 1.0f) * (float)WWW - 1.0f) * 0.5f;
            float tyu = ((gy0 + sgn*dy + 1.0f) * (float)HHH - 1.0f) * 0.5f;
            float tzu = ((gz0 + sgn*dz + 1.0f) * (float)DD  - 1.0f) * 0.5f;
            float ixs = reflectf(txu, (float)WWW);
            float iys = reflectf(tyu, (float)HHH);
            float izs = reflectf(tzu, (float)DD);

            float x0f = floorf(ixs), y0f = floorf(iys), z0f = floorf(izs);
            fx[si] = ixs - x0f;  fy[si] = iys - y0f;  fz[si] = izs - z0f;

            int x0i = (int)x0f; x0i = max(0, min(x0i, WWW-1));
            int y0i = (int)y0f; y0i = max(0, min(y0i, HHH-1));
            int z0i = (int)z0f; z0i = max(0, min(z0i, DD-1));  int z1i = min(z0i+1, DD-1);

            ib[si] = z0i * HW + y0i * WWW + x0i;   // x/y pairs + channel pair baked into g_x8
            oz[si] = (z1i - z0i) * HW;
        }
    }

    const float cLx = -s_sg[7] * (2.0f/3.0f) * sumIr2;
    const float cx  = s_sg[0];

    // ---- Phase 3: per channel-pair: pair-fused quad gathers -> warp stage -> warp GEMM ----
    const int voxg = lane >> 2;    // 0..7 : 4-voxel group within warp
    const int outg = lane & 3;     // 0..3 : 8-output group

    unsigned long long acc[16];
    #pragma unroll
    for (int j = 0; j < 16; j++) acc[j] = 0ull;

    #pragma unroll 1
    for (int p = 0; p < 16; p++) {
        const uint4* __restrict__ b8 = x8n + p * DHW;
        const int c0 = 2 * p;
        float xc0 = xn[c0 * DHW + zyx];
        float xc1 = xn[(c0 + 1) * DHW + zyx];

        float sv0[6], sv1[6];
        #pragma unroll
        for (int si = 0; si < 6; si++) {
            const uint4* pp = b8 + ib[si];
            uint4 q0 = pp[0];        // z0 plane: {ch0 y0pair, ch0 y1pair, ch1 y0pair, ch1 y1pair}
            uint4 q1 = pp[oz[si]];   // z1 plane
            float fxs = fx[si], fys = fy[si], fzs = fz[si];
            // channel c0
            {
                float2 v00 = h2f2(q0.x), v01 = h2f2(q0.y);
                float2 v10 = h2f2(q1.x), v11 = h2f2(q1.y);
                float c00 = v00.x + fxs * (v00.y - v00.x);
                float c01 = v01.x + fxs * (v01.y - v01.x);
                float c10 = v10.x + fxs * (v10.y - v10.x);
                float c11 = v11.x + fxs * (v11.y - v11.x);
                float cc0 = c00 + fys * (c01 - c00);
                float cc1 = c10 + fys * (c11 - c10);
                sv0[si] = cc0 + fzs * (cc1 - cc0);
            }
            // channel c0+1
            {
                float2 v00 = h2f2(q0.z), v01 = h2f2(q0.w);
                float2 v10 = h2f2(q1.z), v11 = h2f2(q1.w);
                float c00 = v00.x + fxs * (v00.y - v00.x);
                float c01 = v01.x + fxs * (v01.y - v01.x);
                float c10 = v10.x + fxs * (v10.y - v10.x);
                float c11 = v11.x + fxs * (v11.y - v11.x);
                float cc0 = c00 + fys * (c01 - c00);
                float cc1 = c10 + fys * (c11 - c10);
                sv1[si] = cc0 + fzs * (cc1 - cc0);
            }
        }

        float tv[16];
        {
            float s0 = sv0[0] + sv0[1], m0 = sv0[0] - sv0[1];
            float s1 = sv0[2] + sv0[3], m1 = sv0[2] - sv0[3];
            float s2 = sv0[4] + sv0[5], m2 = sv0[4] - sv0[5];
            tv[0]  = cx * xc0;
            tv[2]  = cA[0] * s0;
            tv[4]  = cA[1] * s1;
            tv[6]  = cA[2] * s2;
            tv[8]  = cG[0]*m0 + cG[1]*m1 + cG[2]*m2;
            tv[10] = cG[3]*m0 + cG[4]*m1 + cG[5]*m2;
            tv[12] = cG[6]*m0 + cG[7]*m1 + cG[8]*m2;
            tv[14] = cLs[0]*s0 + cLs[1]*s1 + cLs[2]*s2 + cLx * xc0;
        }
        {
            float s0 = sv1[0] + sv1[1], m0 = sv1[0] - sv1[1];
            float s1 = sv1[2] + sv1[3], m1 = sv1[2] - sv1[3];
            float s2 = sv1[4] + sv1[5], m2 = sv1[4] - sv1[5];
            tv[1]  = cx * xc1;
            tv[3]  = cA[0] * s0;
            tv[5]  = cA[1] * s1;
            tv[7]  = cA[2] * s2;
            tv[9]  = cG[0]*m0 + cG[1]*m1 + cG[2]*m2;
            tv[11] = cG[3]*m0 + cG[4]*m1 + cG[5]*m2;
            tv[13] = cG[6]*m0 + cG[7]*m1 + cG[8]*m2;
            tv[15] = cLs[0]*s0 + cLs[1]*s1 + cLs[2]*s2 + cLx * xc1;
        }

        // warp-private double-buffered stage; one syncwarp per iteration
        float* Sbuf = warpS + (p & 1) * 512;
        #pragma unroll
        for (int s = 0; s < 16; s++) Sbuf[s * 32 + lane] = tv[s];
        __syncwarp();

        #pragma unroll
        for (int s = 0; s < 16; s++) {
            const int t     = s >> 1;
            const int half_ = s & 1;
            const float* wb = s_WT + ((t*32 + c0 + half_) << 5) + (outg << 3);
            ulonglong2 q0 = *(const ulonglong2*)wb;
            ulonglong2 q1 = *(const ulonglong2*)(wb + 4);
            const float4 av = *(const float4*)(Sbuf + s * 32 + (voxg << 2));
            unsigned long long a0 = pack2(av.x), a1 = pack2(av.y),
                               a2 = pack2(av.z), a3 = pack2(av.w);
            ffma2(acc[0],  q0.x, a0); ffma2(acc[1],  q0.y, a0);
            ffma2(acc[2],  q1.x, a0); ffma2(acc[3],  q1.y, a0);
            ffma2(acc[4],  q0.x, a1); ffma2(acc[5],  q0.y, a1);
            ffma2(acc[6],  q1.x, a1); ffma2(acc[7],  q1.y, a1);
            ffma2(acc[8],  q0.x, a2); ffma2(acc[9],  q0.y, a2);
            ffma2(acc[10], q1.x, a2); ffma2(acc[11], q1.y, a2);
            ffma2(acc[12], q0.x, a3); ffma2(acc[13], q0.y, a3);
            ffma2(acc[14], q1.x, a3); ffma2(acc[15], q1.y, a3);
        }
    }

    // ---- Phase 4: epilogue — my tile = 4 consecutive voxels x 8 outputs ----
    const int vt   = blockIdx.x * THREADS + wrp * 32 + (voxg << 2);
    const int n2   = vt / DHW;
    const int zyx2 = vt - n2 * DHW;
    const float* __restrict__ xn2 = x + (size_t)n2 * CCH * DHW;
    float* __restrict__ on2       = out + (size_t)n2 * CCH * DHW;
    #pragma unroll
    for (int jj = 0; jj < 4; jj++) {
        int o0 = (outg << 3) + 2*jj;
        float2 d0 = unpack2(acc[0*4 + jj]);
        float2 d1 = unpack2(acc[1*4 + jj]);
        float2 d2 = unpack2(acc[2*4 + jj]);
        float2 d3 = unpack2(acc[3*4 + jj]);
        {
            float4 xv = *(const float4*)(xn2 + (size_t)o0 * DHW + zyx2);
            float b = s_bmix[o0];
            float4 ov = make_float4(xv.x + d0.x + b, xv.y + d1.x + b,
                                    xv.z + d2.x + b, xv.w + d3.x + b);
            *(float4*)(on2 + (size_t)o0 * DHW + zyx2) = ov;
        }
        {
            int o1 = o0 + 1;
            float4 xv = *(const float4*)(xn2 + (size_t)o1 * DHW + zyx2);
            float b = s_bmix[o1];
            float4 ov = make_float4(xv.x + d0.y + b, xv.y + d1.y + b,
                                    xv.z + d2.y + b, xv.w + d3.y + b);
            *(float4*)(on2 + (size_t)o1 * DHW + zyx2) = ov;
        }
    }
}

extern "C" void kernel_launch(void* const* d_in, const int* in_sizes, int n_in,
                              void* d_out, int out_size)
{
    const float* x       = (const float*)d_in[0];
    const float* w_field = (const float*)d_in[1];
    const float* b_field = (const float*)d_in[2];
    const float* gates   = (const float*)d_in[3];
    const float* w_mix   = (const float*)d_in[4];
    const float* b_mix   = (const float*)d_in[5];
    float* out = (float*)d_out;

    (void)cudaFuncSetAttribute(geo_sample3d_kernel,
                               cudaFuncAttributeMaxDynamicSharedMemorySize, SMEM_DYN);

    // one merged prep launch: blocks [0,32) transpose w_mix, rest build g_x8
    prep_kernel<<<32 + (NPAIR + 255) / 256, 256>>>(x, w_mix);

    int total_vox = in_sizes[0] / CCH;                 // 221184
    int blocks = total_vox / THREADS;                  // 864 (exact)
    geo_sample3d_kernel<<<blocks, THREADS, SMEM_DYN>>>(x, w_field, b_field, gates,
                                                       b_mix, out);
}